// round 5
// baseline (speedup 1.0000x reference)
#include <cuda_runtime.h>
#include <cstdint>

// Problem constants (fixed by setup_inputs)
#define BB 4
#define NN 16384
#define MM 128
#define CC 128
#define SS 512
#define ROW 131            // 3 + C floats per sample
#define NBOX (BB*MM)       // 512
#define WPB  (NN/32)       // 512 mask words per box
#define BOXG 16            // boxes per mask-block (128/8 groups)
#define POOLED_ELEMS ((size_t)NBOX * SS * ROW)   // 34,340,864 (divisible by 4)

// Scratch (device globals — no allocation allowed)
__device__ unsigned g_mask[NBOX * WPB];  // [bm][word] inside-bitmask, 1MB
__device__ int g_idx[NBOX * SS];         // first min(cnt,512) inside indices per box
__device__ int g_cnt[NBOX];              // exact inside count

// ---------------------------------------------------------------------------
// Stage 1: mask kernel. Each thread owns one point (registers), loops over a
// group of 16 boxes of its batch (params staged in shared). lane0 of each
// warp stores the 32-bit ballot per box.
// Grid: 2048 blocks x 256 threads (8 box-groups x 64 point-blocks x 4 batches).
// ---------------------------------------------------------------------------
__global__ __launch_bounds__(256)
void mask_kernel(const float* __restrict__ points,
                 const float* __restrict__ boxes) {
    const int blk   = blockIdx.x;        // 0..2047
    const int grp   = blk & 7;           // box group (16 boxes)
    const int pblk  = blk >> 3;          // 0..255
    const int b     = pblk >> 6;         // batch  (64 point-blocks per batch)
    const int pbase = (pblk & 63) * 256; // first point in batch for this block
    const int mbase = grp * BOXG;        // first box in group

    // Box params: p0 = (cx, cy, cz_center, hz), p1 = (cosa, sina, hx, hy)
    __shared__ float4 sb0[BOXG];
    __shared__ float4 sb1[BOXG];

    const int tid = threadIdx.x;
    if (tid < BOXG) {
        const float* box = boxes + (b * MM + mbase + tid) * 7;
        const float cx = box[0];
        const float cy = box[1];
        const float cz = __fadd_rn(box[2], __fmul_rn(box[5], 0.5f));
        const float dx = box[3];
        const float dy = box[4];
        const float dz = box[5];
        const float rz = box[6];
        sb0[tid] = make_float4(cx, cy, cz, __fmul_rn(dz, 0.5f));
        sb1[tid] = make_float4(cosf(-rz), sinf(-rz),
                               __fmul_rn(dx, 0.5f), __fmul_rn(dy, 0.5f));
    }

    const int pi   = pbase + tid;                 // point index within batch
    const float* p = points + ((size_t)b * NN + pi) * 3;
    const float px = p[0];
    const float py = p[1];
    const float pz = p[2];

    __syncthreads();

    const int lane = tid & 31;
    const int word = pi >> 5;                     // mask word within batch
    unsigned* mrow = g_mask + (size_t)(b * MM + mbase) * WPB + word;

    #pragma unroll 4
    for (int m = 0; m < BOXG; m++) {
        const float4 q0 = sb0[m];
        const float4 q1 = sb1[m];
        const float sx = __fsub_rn(px, q0.x);
        const float sy = __fsub_rn(py, q0.y);
        const float sz = __fsub_rn(pz, q0.z);
        // no-FMA-contraction rotate to match XLA mul-then-add ordering
        const float lx = __fsub_rn(__fmul_rn(sx, q1.x), __fmul_rn(sy, q1.y));
        const float ly = __fadd_rn(__fmul_rn(sx, q1.y), __fmul_rn(sy, q1.x));
        const bool inside = (fabsf(lx) < q1.z) && (fabsf(ly) < q1.w)
                          && (fabsf(sz) <= q0.w);
        const unsigned ball = __ballot_sync(0xffffffffu, inside);
        if (lane == 0) mrow[(size_t)m * WPB] = ball;
    }
}

// ---------------------------------------------------------------------------
// Stage 2: compaction. One 512-thread block per box. Block prefix scan over
// per-word popcounts, then expand set bits (stable order) into g_idx[0..511].
// Also writes exact cnt and the empty flag.
// ---------------------------------------------------------------------------
__global__ __launch_bounds__(512)
void compact_kernel(float* __restrict__ flags) {
    const int bm  = blockIdx.x;
    const int t   = threadIdx.x;         // 0..511 (one mask word each)
    const int lane = t & 31;
    const int wid  = t >> 5;             // 0..15

    const unsigned w = g_mask[(size_t)bm * WPB + t];
    const int c = __popc(w);

    // warp inclusive scan of counts
    int incl = c;
    #pragma unroll
    for (int d = 1; d < 32; d <<= 1) {
        int v = __shfl_up_sync(0xffffffffu, incl, d);
        if (lane >= d) incl += v;
    }

    __shared__ int wsum[16];
    __shared__ int stotal;
    if (lane == 31) wsum[wid] = incl;
    __syncthreads();
    if (t < 16) {
        int v = wsum[t];
        #pragma unroll
        for (int d = 1; d < 16; d <<= 1) {
            int u = __shfl_up_sync(0xffffu, v, d);
            if (t >= d) v += u;
        }
        wsum[t] = v;
        if (t == 15) stotal = v;
    }
    __syncthreads();

    const int warp_excl = (wid == 0) ? 0 : wsum[wid - 1];
    int rank = warp_excl + incl - c;     // exclusive prefix = first output slot

    // expand set bits in order until rank hits 512
    unsigned ww = w;
    const int pbase = t * 32;
    while (ww && rank < SS) {
        const int bit = __ffs(ww) - 1;
        ww &= ww - 1;
        g_idx[bm * SS + rank] = pbase + bit;
        rank++;
    }

    if (t == 0) {
        const int total = stotal;
        g_cnt[bm] = total;
        if (flags) flags[bm] = (total > 0) ? 0.0f : 1.0f;
    }
}

// ---------------------------------------------------------------------------
// Stage 3: gather, output-flat. Each thread owns 4 consecutive output floats
// (16B-aligned) -> fully coalesced STG.128 streaming writes, gather reads
// served from L2-resident features.
// ---------------------------------------------------------------------------
__device__ __forceinline__ float fetch_val(const float* __restrict__ points,
                                           const float* __restrict__ feats,
                                           int b, int idx, unsigned col) {
    if (col < 3u)
        return __ldg(points + ((size_t)b * NN + idx) * 3 + col);
    return __ldg(feats + ((size_t)b * NN + idx) * CC + (col - 3u));
}

__global__ __launch_bounds__(256)
void gather_kernel(const float* __restrict__ points,
                   const float* __restrict__ feats,
                   float* __restrict__ out) {
    const unsigned t  = blockIdx.x * 256u + threadIdx.x;
    const unsigned e0 = t * 4u;                        // first output element
    const unsigned row0 = e0 / 131u;                   // mul-hi constant div
    const unsigned row1 = (e0 + 3u) / 131u;

    float4 v;
    if (row0 == row1) {
        // fast path: all 4 elements in one sample row
        const unsigned col = e0 - row0 * 131u;
        const unsigned bm  = row0 >> 9;                // /S
        const unsigned s   = row0 & (SS - 1u);
        const int b   = (int)(bm >> 7);                // /M
        const int cnt = g_cnt[bm];
        if (cnt == 0) {
            v = make_float4(0.f, 0.f, 0.f, 0.f);
        } else {
            const unsigned r = (s < (unsigned)cnt) ? s : (s % (unsigned)cnt);
            const int idx = g_idx[bm * SS + r];
            if (col >= 3u) {
                const float* f = feats + ((size_t)b * NN + idx) * CC + (col - 3u);
                v.x = __ldg(f + 0); v.y = __ldg(f + 1);
                v.z = __ldg(f + 2); v.w = __ldg(f + 3);
            } else {
                v.x = fetch_val(points, feats, b, idx, col + 0u);
                v.y = fetch_val(points, feats, b, idx, col + 1u);
                v.z = fetch_val(points, feats, b, idx, col + 2u);
                v.w = fetch_val(points, feats, b, idx, col + 3u);
            }
        }
    } else {
        // slow path: chunk straddles a row boundary (1 in ~33 threads)
        float tmp[4];
        #pragma unroll
        for (int j = 0; j < 4; j++) {
            const unsigned e   = e0 + j;
            const unsigned row = e / 131u;
            const unsigned col = e - row * 131u;
            const unsigned bm  = row >> 9;
            const unsigned s   = row & (SS - 1u);
            const int b   = (int)(bm >> 7);
            const int cnt = g_cnt[bm];
            if (cnt == 0) {
                tmp[j] = 0.f;
            } else {
                const unsigned r = (s < (unsigned)cnt) ? s : (s % (unsigned)cnt);
                const int idx = g_idx[bm * SS + r];
                tmp[j] = fetch_val(points, feats, b, idx, col);
            }
        }
        v = make_float4(tmp[0], tmp[1], tmp[2], tmp[3]);
    }

    __stcs((float4*)(out) + t, v);
}

extern "C" void kernel_launch(void* const* d_in, const int* in_sizes, int n_in,
                              void* d_out, int out_size) {
    const float* points = (const float*)d_in[0];   // (B, N, 3)
    const float* feats  = (const float*)d_in[1];   // (B, N, C)
    const float* boxes  = (const float*)d_in[2];   // (B, M, 7)
    float* out = (float*)d_out;

    float* flags = ((size_t)out_size >= POOLED_ELEMS + NBOX)
                 ? (out + POOLED_ELEMS) : nullptr;

    mask_kernel<<<2048, 256>>>(points, boxes);
    compact_kernel<<<NBOX, 512>>>(flags);

    // POOLED_ELEMS / 4 = 8,585,216 float4 chunks = 33,536 blocks x 256 threads
    gather_kernel<<<(int)(POOLED_ELEMS / 4 / 256), 256>>>(points, feats, out);
}

// round 6
// speedup vs baseline: 1.4601x; 1.4601x over previous
#include <cuda_runtime.h>
#include <cstdint>

// Problem constants (fixed by setup_inputs)
#define BB 4
#define NN 16384
#define MM 128
#define CC 128
#define SS 512
#define ROW 131            // 3 + C floats per sample
#define NBOX (BB*MM)       // 512
#define WPB  (NN/32)       // 512 mask words per box
#define BOXG 16            // boxes per mask-block (128/8 groups)
#define RPB  8             // rows per gather block
#define POOLED_ELEMS ((size_t)NBOX * SS * ROW)   // 34,340,864

// Scratch (device globals — no allocation allowed)
__device__ unsigned g_mask[NBOX * WPB];  // [bm][word] inside-bitmask, 1MB
__device__ int g_idx[NBOX * SS];         // first min(cnt,512) inside indices per box
__device__ int g_cnt[NBOX];              // exact inside count

// ---------------------------------------------------------------------------
// Stage 1: mask kernel. Each thread owns one point (registers), loops over a
// group of 16 boxes of its batch (params staged in shared). lane0 of each
// warp stores the 32-bit ballot per box.
// Grid: 2048 blocks x 256 threads (8 box-groups x 64 point-blocks x 4 batches).
// ---------------------------------------------------------------------------
__global__ __launch_bounds__(256)
void mask_kernel(const float* __restrict__ points,
                 const float* __restrict__ boxes) {
    const int blk   = blockIdx.x;        // 0..2047
    const int grp   = blk & 7;           // box group (16 boxes)
    const int pblk  = blk >> 3;          // 0..255
    const int b     = pblk >> 6;         // batch  (64 point-blocks per batch)
    const int pbase = (pblk & 63) * 256; // first point in batch for this block
    const int mbase = grp * BOXG;        // first box in group

    // Box params: p0 = (cx, cy, cz_center, hz), p1 = (cosa, sina, hx, hy)
    __shared__ float4 sb0[BOXG];
    __shared__ float4 sb1[BOXG];

    const int tid = threadIdx.x;
    if (tid < BOXG) {
        const float* box = boxes + (b * MM + mbase + tid) * 7;
        const float cx = box[0];
        const float cy = box[1];
        const float cz = __fadd_rn(box[2], __fmul_rn(box[5], 0.5f));
        const float dx = box[3];
        const float dy = box[4];
        const float dz = box[5];
        const float rz = box[6];
        sb0[tid] = make_float4(cx, cy, cz, __fmul_rn(dz, 0.5f));
        sb1[tid] = make_float4(cosf(-rz), sinf(-rz),
                               __fmul_rn(dx, 0.5f), __fmul_rn(dy, 0.5f));
    }

    const int pi   = pbase + tid;                 // point index within batch
    const float* p = points + ((size_t)b * NN + pi) * 3;
    const float px = p[0];
    const float py = p[1];
    const float pz = p[2];

    __syncthreads();

    const int lane = tid & 31;
    const int word = pi >> 5;                     // mask word within batch
    unsigned* mrow = g_mask + (size_t)(b * MM + mbase) * WPB + word;

    #pragma unroll 4
    for (int m = 0; m < BOXG; m++) {
        const float4 q0 = sb0[m];
        const float4 q1 = sb1[m];
        const float sx = __fsub_rn(px, q0.x);
        const float sy = __fsub_rn(py, q0.y);
        const float sz = __fsub_rn(pz, q0.z);
        // no-FMA-contraction rotate to match XLA mul-then-add ordering
        const float lx = __fsub_rn(__fmul_rn(sx, q1.x), __fmul_rn(sy, q1.y));
        const float ly = __fadd_rn(__fmul_rn(sx, q1.y), __fmul_rn(sy, q1.x));
        const bool inside = (fabsf(lx) < q1.z) && (fabsf(ly) < q1.w)
                          && (fabsf(sz) <= q0.w);
        const unsigned ball = __ballot_sync(0xffffffffu, inside);
        if (lane == 0) mrow[(size_t)m * WPB] = ball;
    }
}

// ---------------------------------------------------------------------------
// Stage 2: compaction. One 512-thread block per box. Block prefix scan over
// per-word popcounts, then expand set bits (stable order) into g_idx[0..511].
// Also writes exact cnt and the empty flag.
// ---------------------------------------------------------------------------
__global__ __launch_bounds__(512)
void compact_kernel(float* __restrict__ flags) {
    const int bm  = blockIdx.x;
    const int t   = threadIdx.x;         // 0..511 (one mask word each)
    const int lane = t & 31;
    const int wid  = t >> 5;             // 0..15

    const unsigned w = g_mask[(size_t)bm * WPB + t];
    const int c = __popc(w);

    // warp inclusive scan of counts
    int incl = c;
    #pragma unroll
    for (int d = 1; d < 32; d <<= 1) {
        int v = __shfl_up_sync(0xffffffffu, incl, d);
        if (lane >= d) incl += v;
    }

    __shared__ int wsum[16];
    __shared__ int stotal;
    if (lane == 31) wsum[wid] = incl;
    __syncthreads();
    if (t < 16) {
        int v = wsum[t];
        #pragma unroll
        for (int d = 1; d < 16; d <<= 1) {
            int u = __shfl_up_sync(0xffffu, v, d);
            if (t >= d) v += u;
        }
        wsum[t] = v;
        if (t == 15) stotal = v;
    }
    __syncthreads();

    const int warp_excl = (wid == 0) ? 0 : wsum[wid - 1];
    int rank = warp_excl + incl - c;     // exclusive prefix = first output slot

    // expand set bits in order until rank hits 512
    unsigned ww = w;
    const int pbase = t * 32;
    while (ww && rank < SS) {
        const int bit = __ffs(ww) - 1;
        ww &= ww - 1;
        g_idx[bm * SS + rank] = pbase + bit;
        rank++;
    }

    if (t == 0) {
        const int total = stotal;
        g_cnt[bm] = total;
        if (flags) flags[bm] = (total > 0) ? 0.0f : 1.0f;
    }
}

// ---------------------------------------------------------------------------
// Stage 3: gather. 8 warps per block, one row per warp, staged through shared
// memory, then written out as aligned, fully-coalesced float4 streaming stores.
// Block span = 8*131 = 1048 floats (16B-aligned since 1048 % 4 == 0).
// ---------------------------------------------------------------------------
__global__ __launch_bounds__(256)
void phase2_kernel(const float* __restrict__ points,
                   const float* __restrict__ feats,
                   float* __restrict__ out) {
    __shared__ __align__(16) float srow[RPB * ROW];   // 4192 B

    const int wid  = threadIdx.x >> 5;
    const int lane = threadIdx.x & 31;
    const int row0 = blockIdx.x * RPB;          // first sample row of block
    const int row  = row0 + wid;                // this warp's row

    const int s  = row & (SS - 1);
    const int bm = row >> 9;                    // /S
    const int b  = bm >> 7;                     // /M

    float* o = srow + wid * ROW;

    const int cnt = g_cnt[bm];
    if (cnt == 0) {
        #pragma unroll
        for (int j = lane; j < ROW; j += 32) o[j] = 0.0f;
    } else {
        const int r   = (s < cnt) ? s : (s % cnt);
        const int idx = g_idx[bm * SS + r];

        const float*  p = points + ((size_t)b * NN + idx) * 3;
        const float4* f = (const float4*)(feats + ((size_t)b * NN + idx) * CC);

        if (lane < 3) o[lane] = p[lane];

        const float4 v = __ldg(f + lane);       // 32 lanes x float4 = full row
        float* od = o + 3 + lane * 4;
        od[0] = v.x; od[1] = v.y; od[2] = v.z; od[3] = v.w;
    }
    __syncthreads();

    // Coalesced streaming copy of the 1048-float block span (262 float4s)
    const float4* src = (const float4*)srow;
    float4* dst = (float4*)(out + (size_t)row0 * ROW);
    const int t = threadIdx.x;
    __stcs(dst + t, src[t]);
    if (t < (RPB * ROW / 4 - 256)) __stcs(dst + 256 + t, src[256 + t]);
}

extern "C" void kernel_launch(void* const* d_in, const int* in_sizes, int n_in,
                              void* d_out, int out_size) {
    const float* points = (const float*)d_in[0];   // (B, N, 3)
    const float* feats  = (const float*)d_in[1];   // (B, N, C)
    const float* boxes  = (const float*)d_in[2];   // (B, M, 7)
    float* out = (float*)d_out;

    float* flags = ((size_t)out_size >= POOLED_ELEMS + NBOX)
                 ? (out + POOLED_ELEMS) : nullptr;

    mask_kernel<<<2048, 256>>>(points, boxes);
    compact_kernel<<<NBOX, 512>>>(flags);

    // 262144 rows / 8 rows per block = 32768 blocks
    phase2_kernel<<<(NBOX * SS) / RPB, 256>>>(points, feats, out);
}

// round 8
// speedup vs baseline: 1.5996x; 1.0956x over previous
#include <cuda_runtime.h>
#include <cstdint>

// Problem constants (fixed by setup_inputs)
#define BB 4
#define NN 16384
#define MM 128
#define CC 128
#define SS 512
#define ROW 131            // 3 + C floats per sample
#define NBOX (BB*MM)       // 512
#define WPB  (NN/32)       // 512 mask words per box
#define BOXG 16            // boxes per mask-block (128/8 groups)
#define POOLED_ELEMS ((size_t)NBOX * SS * ROW)   // 34,340,864

// Scratch (device globals — no allocation allowed)
__device__ unsigned g_mask[NBOX * WPB];  // [bm][word] inside-bitmask, 1MB
__device__ int g_idx[NBOX * SS];         // first min(cnt,512) inside indices per box
__device__ int g_cnt[NBOX];              // exact inside count

// ---------------------------------------------------------------------------
// Stage 1: mask kernel (issue-bound at ~10us).
// ---------------------------------------------------------------------------
__global__ __launch_bounds__(256)
void mask_kernel(const float* __restrict__ points,
                 const float* __restrict__ boxes) {
    const int blk   = blockIdx.x;        // 0..2047
    const int grp   = blk & 7;           // box group (16 boxes)
    const int pblk  = blk >> 3;          // 0..255
    const int b     = pblk >> 6;         // batch
    const int pbase = (pblk & 63) * 256;
    const int mbase = grp * BOXG;

    __shared__ float4 sb0[BOXG];
    __shared__ float4 sb1[BOXG];

    const int tid = threadIdx.x;
    if (tid < BOXG) {
        const float* box = boxes + (b * MM + mbase + tid) * 7;
        const float cz = __fadd_rn(box[2], __fmul_rn(box[5], 0.5f));
        const float rz = box[6];
        sb0[tid] = make_float4(box[0], box[1], cz, __fmul_rn(box[5], 0.5f));
        sb1[tid] = make_float4(cosf(-rz), sinf(-rz),
                               __fmul_rn(box[3], 0.5f), __fmul_rn(box[4], 0.5f));
    }

    const int pi   = pbase + tid;
    const float* p = points + ((size_t)b * NN + pi) * 3;
    const float px = p[0];
    const float py = p[1];
    const float pz = p[2];

    __syncthreads();

    const int lane = tid & 31;
    const int word = pi >> 5;
    unsigned* mrow = g_mask + (size_t)(b * MM + mbase) * WPB + word;

    #pragma unroll 4
    for (int m = 0; m < BOXG; m++) {
        const float4 q0 = sb0[m];
        const float4 q1 = sb1[m];
        const float sx = __fsub_rn(px, q0.x);
        const float sy = __fsub_rn(py, q0.y);
        const float sz = __fsub_rn(pz, q0.z);
        // no-FMA-contraction rotate to match XLA mul-then-add ordering
        const float lx = __fsub_rn(__fmul_rn(sx, q1.x), __fmul_rn(sy, q1.y));
        const float ly = __fadd_rn(__fmul_rn(sx, q1.y), __fmul_rn(sy, q1.x));
        const bool inside = (fabsf(lx) < q1.z) && (fabsf(ly) < q1.w)
                          && (fabsf(sz) <= q0.w);
        const unsigned ball = __ballot_sync(0xffffffffu, inside);
        if (lane == 0) mrow[(size_t)m * WPB] = ball;
    }
}

// ---------------------------------------------------------------------------
// Stage 2: compaction (unchanged).
// ---------------------------------------------------------------------------
__global__ __launch_bounds__(512)
void compact_kernel(float* __restrict__ flags) {
    const int bm  = blockIdx.x;
    const int t   = threadIdx.x;
    const int lane = t & 31;
    const int wid  = t >> 5;

    const unsigned w = g_mask[(size_t)bm * WPB + t];
    const int c = __popc(w);

    int incl = c;
    #pragma unroll
    for (int d = 1; d < 32; d <<= 1) {
        int v = __shfl_up_sync(0xffffffffu, incl, d);
        if (lane >= d) incl += v;
    }

    __shared__ int wsum[16];
    __shared__ int stotal;
    if (lane == 31) wsum[wid] = incl;
    __syncthreads();
    if (t < 16) {
        int v = wsum[t];
        #pragma unroll
        for (int d = 1; d < 16; d <<= 1) {
            int u = __shfl_up_sync(0xffffu, v, d);
            if (t >= d) v += u;
        }
        wsum[t] = v;
        if (t == 15) stotal = v;
    }
    __syncthreads();

    const int warp_excl = (wid == 0) ? 0 : wsum[wid - 1];
    int rank = warp_excl + incl - c;

    unsigned ww = w;
    const int pbase = t * 32;
    while (ww && rank < SS) {
        const int bit = __ffs(ww) - 1;
        ww &= ww - 1;
        g_idx[bm * SS + rank] = pbase + bit;
        rank++;
    }

    if (t == 0) {
        const int total = stotal;
        g_cnt[bm] = total;
        if (flags) flags[bm] = (total > 0) ? 0.0f : 1.0f;
    }
}

// ---------------------------------------------------------------------------
// Stage 3: gather with register realignment. One warp per row.
// Read:  1 aligned LDG.128 per lane (full 128-float feature row).
// Write: registers rotated across lanes by a0 = row&3 positions via shfl so
//        each lane stores one ALIGNED float4 of the output row (STG.128),
//        plus <=3 scalar head/tail stores on lanes 0/31.
// ---------------------------------------------------------------------------
__global__ __launch_bounds__(256)
void phase2_kernel(const float* __restrict__ points,
                   const float* __restrict__ feats,
                   float* __restrict__ out) {
    const int gwarp = (int)((blockIdx.x * blockDim.x + threadIdx.x) >> 5);
    const int lane  = threadIdx.x & 31;
    const int row = gwarp;
    const int s  = row & (SS - 1);
    const int bm = row >> 9;            // /S
    const int b  = bm >> 7;             // /M
    const int a0 = row & 3;             // first 16B-aligned float offset in row

    float* o = out + (size_t)row * ROW;

    const int cnt = g_cnt[bm];

    float4 v = make_float4(0.f, 0.f, 0.f, 0.f);
    float px = 0.f, py = 0.f, pz = 0.f;

    if (cnt != 0) {
        const int r   = (s < cnt) ? s : (s % cnt);
        const int idx = g_idx[bm * SS + r];
        const float4* f = (const float4*)(feats + ((size_t)b * NN + idx) * CC);
        v = __ldg(f + lane);            // cols 4*lane .. 4*lane+3
        if (lane == 0) {
            const float* p = points + ((size_t)b * NN + idx) * 3;
            px = __ldg(p + 0); py = __ldg(p + 1); pz = __ldg(p + 2);
        }
    }

    // prev-lane components (lane 0 substitutes the point coords)
    float pvy = __shfl_up_sync(0xffffffffu, v.y, 1);
    float pvz = __shfl_up_sync(0xffffffffu, v.z, 1);
    float pvw = __shfl_up_sync(0xffffffffu, v.w, 1);
    if (lane == 0) { pvy = px; pvz = py; pvw = pz; }

    // lane k's aligned quad = row floats [a0+4k, a0+4k+4)
    float4 q;
    if      (a0 == 0) q = make_float4(pvy, pvz, pvw, v.x);
    else if (a0 == 1) q = make_float4(pvz, pvw, v.x, v.y);
    else if (a0 == 2) q = make_float4(pvw, v.x, v.y, v.z);
    else              q = v;

    __stcs((float4*)(o + a0) + lane, q);

    if (lane == 0) {                    // head floats [0, a0): points
        if (a0 > 0) __stcs(o + 0, px);
        if (a0 > 1) __stcs(o + 1, py);
        if (a0 > 2) __stcs(o + 2, pz);
    }
    if (lane == 31) {                   // tail floats [a0+128, 131)
        if (a0 == 0) { __stcs(o + 128, v.y); __stcs(o + 129, v.z); __stcs(o + 130, v.w); }
        else if (a0 == 1) { __stcs(o + 129, v.z); __stcs(o + 130, v.w); }
        else if (a0 == 2) { __stcs(o + 130, v.w); }
    }
}

extern "C" void kernel_launch(void* const* d_in, const int* in_sizes, int n_in,
                              void* d_out, int out_size) {
    const float* points = (const float*)d_in[0];   // (B, N, 3)
    const float* feats  = (const float*)d_in[1];   // (B, N, C)
    const float* boxes  = (const float*)d_in[2];   // (B, M, 7)
    float* out = (float*)d_out;

    float* flags = ((size_t)out_size >= POOLED_ELEMS + NBOX)
                 ? (out + POOLED_ELEMS) : nullptr;

    mask_kernel<<<2048, 256>>>(points, boxes);
    compact_kernel<<<NBOX, 512>>>(flags);

    const int total_warps = NBOX * SS;             // one warp per sample row
    phase2_kernel<<<total_warps / 8, 256>>>(points, feats, out);
}